// round 2
// baseline (speedup 1.0000x reference)
#include <cuda_runtime.h>

// Hybrid_Conv2d: out[b] = conv2d(x[b], W_0 + cov[b]*W_1), 3x3, pad 1, stride 1
// B=32, CIN=COUT=64, H=W=128.
//
// Round 1: fp32 direct conv baseline.
//  - Each block: one batch b, 8 output channels, 16 output rows, all 128 cols.
//  - Per-block weights (8 co x 64 ci x 9) built once in SMEM from W0 + cov[b]*W1.
//  - Input staged in SMEM in chunks of 8 channels x 18 rows x 130 cols (halo).
//  - 512 threads: thread = (col 0..127, rowgroup 0..3); each thread accumulates
//    8 couts x 4 rows = 32 fp32 accumulators.

#define B_       32
#define C_       64
#define HW_      128
#define CO_T     8
#define RH       16
#define CI_T     8
#define PAD_H    18        // RH + 2 halo rows
#define PAD_W    130       // 128 + 2 halo cols
#define NTHREADS 512

#define SW_ELEMS  (CO_T * C_ * 9)          // 4608 floats  (18432 B)
#define SIN_ELEMS (CI_T * PAD_H * PAD_W)   // 18720 floats (74880 B)
#define SMEM_BYTES ((SW_ELEMS + SIN_ELEMS) * 4)   // 93312 B

extern __shared__ float smem_dyn[];

__global__ __launch_bounds__(NTHREADS, 1)
void hybrid_conv2d_kernel(const float* __restrict__ x,
                          const float* __restrict__ cov,
                          const float* __restrict__ W0,
                          const float* __restrict__ W1,
                          float* __restrict__ out) {
    float* sW  = smem_dyn;             // [CO_T][C_][9]
    float* sIn = smem_dyn + SW_ELEMS;  // [CI_T][PAD_H][PAD_W]

    const int b       = blockIdx.z;
    const int rowTile = blockIdx.y;
    const int coG     = blockIdx.x;
    const int tid     = threadIdx.x;
    const int xcol    = tid & 127;     // output column
    const int r0      = (tid >> 7) * 4; // first of 4 output rows (local)

    // ---- build per-batch weight slice: W0 + cov[b]*W1, 8 couts x 64 ci x 9 ----
    const float cv = cov[b];
    for (int i = tid; i < SW_ELEMS; i += NTHREADS) {
        int co  = i / (C_ * 9);
        int rem = i - co * (C_ * 9);
        int g   = ((coG * CO_T + co) * C_) * 9 + rem;
        sW[i] = W0[g] + cv * W1[g];
    }

    float acc[CO_T][4];
    #pragma unroll
    for (int co = 0; co < CO_T; co++)
        #pragma unroll
        for (int r = 0; r < 4; r++)
            acc[co][r] = 0.0f;

    const int y0 = rowTile * RH;

    for (int ci0 = 0; ci0 < C_; ci0 += CI_T) {
        __syncthreads();  // prev compute done (and, on iter 0, weight build done)

        // ---- stage input chunk: CI_T channels x PAD_H rows x PAD_W cols ----
        for (int e = tid; e < SIN_ELEMS; e += NTHREADS) {
            int ci  = e / (PAD_H * PAD_W);
            int rem = e - ci * (PAD_H * PAD_W);
            int row = rem / PAD_W;
            int col = rem - row * PAD_W;
            int gy  = y0 + row - 1;
            int gx  = col - 1;
            float v = 0.0f;
            if ((unsigned)gy < HW_ && (unsigned)gx < HW_)
                v = x[((b * C_ + ci0 + ci) * HW_ + gy) * HW_ + gx];
            sIn[e] = v;
        }
        __syncthreads();

        // ---- compute ----
        #pragma unroll
        for (int ci = 0; ci < CI_T; ci++) {
            // 6 input rows x 3 cols cover 4 output rows of a 3x3 window
            float in[6][3];
            #pragma unroll
            for (int rr = 0; rr < 6; rr++)
                #pragma unroll
                for (int cc = 0; cc < 3; cc++)
                    in[rr][cc] = sIn[(ci * PAD_H + r0 + rr) * PAD_W + xcol + cc];

            #pragma unroll
            for (int co = 0; co < CO_T; co++) {
                const float* wp = &sW[(co * C_ + ci0 + ci) * 9];
                float w[9];
                #pragma unroll
                for (int k = 0; k < 9; k++) w[k] = wp[k];

                #pragma unroll
                for (int r = 0; r < 4; r++)
                    #pragma unroll
                    for (int ky = 0; ky < 3; ky++)
                        #pragma unroll
                        for (int kx = 0; kx < 3; kx++)
                            acc[co][r] = fmaf(w[ky * 3 + kx], in[r + ky][kx], acc[co][r]);
            }
        }
    }

    // ---- store ----
    #pragma unroll
    for (int co = 0; co < CO_T; co++) {
        const int cog = coG * CO_T + co;
        #pragma unroll
        for (int r = 0; r < 4; r++) {
            const int y = y0 + r0 + r;
            out[((b * C_ + cog) * HW_ + y) * HW_ + xcol] = acc[co][r];
        }
    }
}

extern "C" void kernel_launch(void* const* d_in, const int* in_sizes, int n_in,
                              void* d_out, int out_size) {
    (void)in_sizes; (void)n_in; (void)out_size;
    const float* x   = (const float*)d_in[0];
    const float* cov = (const float*)d_in[1];
    const float* W0  = (const float*)d_in[2];
    const float* W1  = (const float*)d_in[3];
    float* out = (float*)d_out;

    cudaFuncSetAttribute(hybrid_conv2d_kernel,
                         cudaFuncAttributeMaxDynamicSharedMemorySize, SMEM_BYTES);

    dim3 grid(C_ / CO_T, HW_ / RH, B_);  // (8 cout groups, 8 row tiles, 32 batches)
    hybrid_conv2d_kernel<<<grid, NTHREADS, SMEM_BYTES>>>(x, cov, W0, W1, out);
}

// round 5
// speedup vs baseline: 3.9030x; 3.9030x over previous
#include <cuda_runtime.h>
#include <stdint.h>

// Hybrid_Conv2d via warp-level mma.sync tf32 implicit GEMM (sm_80+ path;
// tcgen05 is unavailable because the harness compiles PTX at compute_103
// without the 'a' arch-variant suffix).
//
// out[b] = conv2d(x[b], W0 + cov[b]*W1), 3x3 pad 1, B=32, C=64, 128x128.
//
// Prologue kernel: Wc[b][tap][ci][co] = tf32(W0 + cov[b]*W1)   (4.7 MB static)
// Conv kernel: CTA = (b, image row y). GEMM D[128 px][64 co], K = 576
//   staged as 18 iters of (tap, ci-half of 32). A = im2col slice in SMEM
//   [ci][px] (stride 136 -> conflict-free), B = weights [ci][co] (stride 72).
//   8 warps, each owns 16 px; 8 n-tiles of 8 cout; acc in registers.

#define HW_   128
#define C_    64
#define B_    32
#define NT    256

#define SA_STRIDE 136          // floats; bank(ti*8+g) all distinct
#define SB_STRIDE 72
#define SA_ELEMS  (32 * SA_STRIDE)   // 4352
#define SB_ELEMS  (32 * SB_STRIDE)   // 2304
#define BUF_ELEMS (SA_ELEMS + SB_ELEMS)
#define SMEM_BYTES (2 * BUF_ELEMS * 4)   // 53248

__device__ uint32_t d_Wc[B_ * 9 * C_ * C_];   // [b][tap][ci][co], tf32 bits

static __device__ __forceinline__ uint32_t f2tf32(float f) {
    uint32_t r;
    asm("cvt.rna.tf32.f32 %0, %1;" : "=r"(r) : "f"(f));
    return r;
}

__global__ void build_weights_kernel(const float* __restrict__ W0,
                                     const float* __restrict__ W1,
                                     const float* __restrict__ cov) {
    const int off = blockIdx.x;        // tap 0..8
    const int b   = blockIdx.y;
    const float cv = cov[b];
    for (int i = threadIdx.x; i < C_ * C_; i += NT) {
        const int ci = i >> 6, co = i & 63;
        const int g = (co * C_ + ci) * 9 + off;
        d_Wc[((b * 9 + off) * C_ + ci) * C_ + co] = f2tf32(W0[g] + cv * W1[g]);
    }
}

extern __shared__ float smem_dyn[];

__global__ __launch_bounds__(NT, 3)
void hybrid_conv_mma_kernel(const float* __restrict__ x,
                            float* __restrict__ out) {
    const int tid = threadIdx.x;
    const int y   = blockIdx.x;        // image row
    const int b   = blockIdx.y;
    const int wa  = tid >> 5;          // warp 0..7 -> px tile [wa*16, wa*16+16)
    const int lid = tid & 31;
    const int g   = lid >> 2;          // groupID
    const int ti  = lid & 3;           // threadID_in_group

    float acc[8][4];
    #pragma unroll
    for (int nt = 0; nt < 8; nt++)
        #pragma unroll
        for (int r = 0; r < 4; r++) acc[nt][r] = 0.0f;

    const int px   = tid & 127;
    const int half = tid >> 7;

    // ---- stage(it, buf): fill sA [32 ci][128 px] and sB [32 ci][64 co] ----
    auto stage = [&](int it, float* buf) {
        const int off = it >> 1;              // tap
        const int ci0 = (it & 1) * 32;
        const int ky = off / 3, kx = off % 3;
        const int gy = y + ky - 1;
        const int gx = px + kx - 1;
        const bool ok = ((unsigned)gy < (unsigned)HW_) & ((unsigned)gx < (unsigned)HW_);
        const float* xsrc = x + (((size_t)(b * C_ + ci0 + half * 16) * HW_
                                 + (ok ? gy : 0)) * HW_) + (ok ? gx : 0);
        float* sA = buf;
        #pragma unroll
        for (int j = 0; j < 16; j++) {
            const float v = ok ? xsrc[(size_t)j * (HW_ * HW_)] : 0.0f;
            sA[(half * 16 + j) * SA_STRIDE + px] = __uint_as_float(f2tf32(v));
        }
        uint32_t* sB = (uint32_t*)(buf + SA_ELEMS);
        const uint32_t* wsrc = &d_Wc[((b * 9 + off) * C_ + ci0) * C_];
        #pragma unroll
        for (int i = 0; i < 8; i++) {
            const int idx = i * NT + tid;     // 0..2047
            const int ci = idx >> 6, co = idx & 63;
            sB[ci * SB_STRIDE + co] = wsrc[idx];
        }
    };

    // ---- compute(buf): 4 k-steps x 8 n-tiles of m16n8k8 ----
    auto compute = [&](const float* buf) {
        const uint32_t* sA = (const uint32_t*)buf;
        const uint32_t* sB = (const uint32_t*)(buf + SA_ELEMS);
        #pragma unroll
        for (int ks = 0; ks < 4; ks++) {
            const int k = ks * 8;
            const uint32_t a0 = sA[(k + ti) * SA_STRIDE + wa * 16 + g];
            const uint32_t a1 = sA[(k + ti) * SA_STRIDE + wa * 16 + g + 8];
            const uint32_t a2 = sA[(k + ti + 4) * SA_STRIDE + wa * 16 + g];
            const uint32_t a3 = sA[(k + ti + 4) * SA_STRIDE + wa * 16 + g + 8];
            #pragma unroll
            for (int nt = 0; nt < 8; nt++) {
                const uint32_t b0 = sB[(k + ti) * SB_STRIDE + nt * 8 + g];
                const uint32_t b1 = sB[(k + ti + 4) * SB_STRIDE + nt * 8 + g];
                asm volatile(
                    "mma.sync.aligned.m16n8k8.row.col.f32.tf32.tf32.f32 "
                    "{%0,%1,%2,%3}, {%4,%5,%6,%7}, {%8,%9}, {%0,%1,%2,%3};"
                    : "+f"(acc[nt][0]), "+f"(acc[nt][1]),
                      "+f"(acc[nt][2]), "+f"(acc[nt][3])
                    : "r"(a0), "r"(a1), "r"(a2), "r"(a3), "r"(b0), "r"(b1));
            }
        }
    };

    stage(0, smem_dyn);
    #pragma unroll 2
    for (int it = 0; it < 18; it++) {
        __syncthreads();
        if (it < 17) stage(it + 1, smem_dyn + ((it + 1) & 1) * BUF_ELEMS);
        compute(smem_dyn + (it & 1) * BUF_ELEMS);
    }

    // ---- epilogue: acc -> out[b][co][y][px] ----
    const int row0 = wa * 16 + g;
    float* ob = out + ((size_t)b * C_ * HW_ + y) * HW_;
    #pragma unroll
    for (int nt = 0; nt < 8; nt++) {
        const int n = nt * 8 + 2 * ti;
        ob[(size_t)n       * (HW_ * HW_) + row0]     = acc[nt][0];
        ob[(size_t)(n + 1) * (HW_ * HW_) + row0]     = acc[nt][1];
        ob[(size_t)n       * (HW_ * HW_) + row0 + 8] = acc[nt][2];
        ob[(size_t)(n + 1) * (HW_ * HW_) + row0 + 8] = acc[nt][3];
    }
}

extern "C" void kernel_launch(void* const* d_in, const int* in_sizes, int n_in,
                              void* d_out, int out_size) {
    (void)in_sizes; (void)n_in; (void)out_size;
    const float* x   = (const float*)d_in[0];
    const float* cov = (const float*)d_in[1];
    const float* W0  = (const float*)d_in[2];
    const float* W1  = (const float*)d_in[3];
    float* out = (float*)d_out;

    build_weights_kernel<<<dim3(9, B_), NT>>>(W0, W1, cov);

    cudaFuncSetAttribute(hybrid_conv_mma_kernel,
                         cudaFuncAttributeMaxDynamicSharedMemorySize, SMEM_BYTES);
    hybrid_conv_mma_kernel<<<dim3(HW_, B_), NT, SMEM_BYTES>>>(x, out);
}